// round 13
// baseline (speedup 1.0000x reference)
#include <cuda_runtime.h>
#include <cuda_fp16.h>
#include <stdint.h>

// ============================================================================
// SparseGradLinear, single fused persistent-dataflow kernel (fp16 HMMA):
//   conv  : x -> fp16 (per row-block), U -> fp16          (bids 0..257)
//   phase1: h  = threshold(fp16(x) @ fp16(U)^T)           (bids 258..1793)
//   W2    : partials + reduce -> fp16 W2                  (bids 1794..2387)
//   phase2: out = h @ W2^T + bias                         (bids 2388..3923)
// R13: critical path (converters -> phase1) leads the grid; W2 prep is
// dispatched mid-stream and overlaps under phase-1 (R12 lesson: prep at the
// grid FRONT serializes into the first waves). All dep edges -> lower bids.
// ============================================================================

#define DIM    768
#define MROWS  32768
#define MBLKS  (MROWS / 128)    // 256
#define NBLKS  (DIM / 128)      // 6
#define NT1    (MBLKS * NBLKS)  // 1536
#define NCONV  MBLKS            // 256 x-converters
#define NUCONV 2
#define NW2P   576
#define NRED   18
#define BASEP1 (NCONV + NUCONV)     // 258
#define BASEW2 (BASEP1 + NT1)       // 1794
#define BASERD (BASEW2 + NW2P)      // 2370
#define BASEP2 (BASERD + NRED)      // 2388
#define GRIDSZ (BASEP2 + NT1)       // 3924

__device__ __half    g_x0[(size_t)MROWS * DIM];
__device__ __half    g_h0[(size_t)MROWS * DIM];
__device__ __half    g_u0[DIM * DIM];
__device__ __half    g_w20[DIM * DIM];
__device__ float     g_w2part[4][DIM * DIM];
__device__ unsigned  g_xready[MBLKS];
__device__ unsigned  g_uready;
__device__ unsigned  g_ready[MBLKS];
__device__ unsigned  g_p0done;
__device__ unsigned  g_w2done;

// ---- helpers ----
__device__ __forceinline__ uint32_t smem_u32(const void* p) {
    uint32_t a;
    asm("{ .reg .u64 t; cvta.to.shared.u64 t, %1; cvt.u32.u64 %0, t; }"
        : "=r"(a) : "l"(p));
    return a;
}
__device__ __forceinline__ void cp16(uint32_t dst, const void* src) {
    asm volatile("cp.async.cg.shared.global [%0], [%1], 16;" :: "r"(dst), "l"(src));
}
__device__ __forceinline__ void ldsm4(uint32_t* r, uint32_t addr) {
    asm volatile("ldmatrix.sync.aligned.m8n8.x4.shared.b16 {%0,%1,%2,%3}, [%4];"
                 : "=r"(r[0]), "=r"(r[1]), "=r"(r[2]), "=r"(r[3]) : "r"(addr));
}
__device__ __forceinline__ void mma16816(float* d, const uint32_t* a,
                                         uint32_t b0, uint32_t b1) {
    asm volatile(
        "mma.sync.aligned.m16n8k16.row.col.f32.f16.f16.f32 "
        "{%0,%1,%2,%3}, {%4,%5,%6,%7}, {%8,%9}, {%0,%1,%2,%3};"
        : "+f"(d[0]), "+f"(d[1]), "+f"(d[2]), "+f"(d[3])
        : "r"(a[0]), "r"(a[1]), "r"(a[2]), "r"(a[3]), "r"(b0), "r"(b1));
}
__device__ __forceinline__ void spin_until(const unsigned* flag, unsigned target) {
    unsigned v;
    while (true) {
        asm volatile("ld.acquire.gpu.global.u32 %0, [%1];"
                     : "=r"(v) : "l"(flag) : "memory");
        if (v >= target) break;
        __nanosleep(200);
    }
}
__device__ __forceinline__ void release_add(unsigned* flag) {
    asm volatile("red.release.gpu.global.add.u32 [%0], 1;" :: "l"(flag) : "memory");
}
__device__ __forceinline__ void cvt_store(const float4* src, __half* dst, size_t i) {
    float4 v = src[i];
    __half2 a, b;
    a.x = __float2half_rn(v.x); a.y = __float2half_rn(v.y);
    b.x = __float2half_rn(v.z); b.y = __float2half_rn(v.w);
    __half2* p = (__half2*)(dst + i * 4);
    p[0] = a; p[1] = b;
}

// ============================================================================
// Fused kernel — mainloop tile config
// ============================================================================
#define NCHUNK 24            // 768 / 32
#define BKB    64            // bytes of K per chunk-row (32 fp16)
#define ROWB   80            // padded row stride in bytes
#define MATB   (128 * ROWB)  // 10240 per operand tile
#define NSTAGE 4
#define STB    (2 * MATB)    // A + B per stage = 20480
#define GEMM_SMEM (NSTAGE * STB)   // 81920 -> 2 CTAs/SM

__global__ void __launch_bounds__(256, 2)
fused_all(const float* __restrict__ Xf, const float* __restrict__ Uf,
          const float* __restrict__ VT, const float* __restrict__ Wt,
          float* __restrict__ outF, const float* __restrict__ bias)
{
    extern __shared__ char smem[];
    const int bid = blockIdx.x;
    const int tid = threadIdx.x;

    // ===================== converters: X (per row-block) ====================
    if (bid < NCONV) {
        const int mb = bid;
        const float4* src = (const float4*)(Xf + (size_t)mb * 128 * DIM);
        __half* dst = g_x0 + (size_t)mb * 128 * DIM;
        const int n4 = 128 * DIM / 4;   // 24576
        for (int i = tid; i < n4; i += 256) cvt_store(src, dst, i);
        __threadfence();
        __syncthreads();
        if (tid == 0) release_add(&g_xready[mb]);
        return;
    }

    // ===================== converters: U =====================================
    if (bid < BASEP1) {
        const int r = bid - NCONV;     // 0..1
        const float4* src = (const float4*)Uf;
        const int n4 = DIM * DIM / 4;  // 147456
        for (int i = r * 256 + tid; i < n4; i += NUCONV * 256)
            cvt_store(src, g_u0, i);
        __threadfence();
        __syncthreads();
        if (tid == 0) release_add(&g_uready);
        return;
    }

    // ===================== W2 partials (fp32 SIMT) ==========================
    if (bid >= BASEW2 && bid < BASERD) {
        float* As = (float*)smem;                  // [16][68]
        float* Bs = (float*)(smem + 16 * 68 * 4);  // [16][64]

        const int w = bid - BASEW2;
        const int kz = w / 144;
        const int q  = w % 144;
        const int bp = (q / 12) * 64;
        const int bc = (q % 12) * 64;
        const int kbeg = kz * (DIM / 4);
        const int kend = kbeg + (DIM / 4);
        float* C = &g_w2part[kz][0];

        const int tx = tid & 15;
        const int ty = tid >> 4;

        float acc[4][4] = {};

        for (int k0 = kbeg; k0 < kend; k0 += 16) {
            {
                const int r = tid >> 2;
                const int o4 = (tid & 3) * 4;
                float4 av = *(const float4*)(VT + (size_t)(bp + r) * DIM + k0 + o4);
                As[(o4 + 0) * 68 + r] = av.x; As[(o4 + 1) * 68 + r] = av.y;
                As[(o4 + 2) * 68 + r] = av.z; As[(o4 + 3) * 68 + r] = av.w;
            }
            {
                const int o  = tid >> 4;
                const int c4 = (tid & 15) * 4;
                *(float4*)&Bs[o * 64 + c4] =
                    *(const float4*)(Wt + (size_t)(k0 + o) * DIM + bc + c4);
            }
            __syncthreads();
#pragma unroll
            for (int o = 0; o < 16; o++) {
                float a[4], b[4];
#pragma unroll
                for (int i = 0; i < 4; i++) a[i] = As[o * 68 + ty * 4 + i];
#pragma unroll
                for (int j = 0; j < 4; j++) b[j] = Bs[o * 64 + tx * 4 + j];
#pragma unroll
                for (int i = 0; i < 4; i++)
#pragma unroll
                    for (int j = 0; j < 4; j++) acc[i][j] += a[i] * b[j];
            }
            __syncthreads();
        }

#pragma unroll
        for (int i = 0; i < 4; i++)
#pragma unroll
            for (int j = 0; j < 4; j++)
                C[(size_t)(bp + ty * 4 + i) * DIM + bc + tx * 4 + j] = acc[i][j];

        __threadfence();
        __syncthreads();
        if (tid == 0) release_add(&g_p0done);
        return;
    }

    // ===================== W2 reduce -> fp16 ================================
    if (bid >= BASERD && bid < BASEP2) {
        if (tid == 0) spin_until(&g_p0done, NW2P);
        __syncthreads();

        const int r = bid - BASERD;        // 0..17
        const int n = DIM * DIM;
        const float* P = &g_w2part[0][0];
        for (int i = r * 256 + tid; i < n; i += NRED * 256) {
            float v = P[i] + P[i + n] + P[i + 2 * n] + P[i + 3 * n];
            g_w20[i] = __float2half_rn(v);
        }
        __threadfence();
        __syncthreads();
        if (tid == 0) release_add(&g_w2done);
        return;
    }

    // ===================== phases 1 & 2: main GEMMs =========================
    const bool ph2 = (bid >= BASEP2);
    const int idx = ph2 ? bid - BASEP2 : bid - BASEP1;
    const int mb = idx / NBLKS;
    const int nb = idx % NBLKS;
    const int bm = mb * 128;
    const int bn = nb * 128;

    const int lane = tid & 31;
    const int wid  = tid >> 5;
    const int wm   = wid >> 2;
    const int wn   = wid & 3;

    if (tid == 0) {
        if (ph2) {
            spin_until(&g_w2done, NRED);
            spin_until(&g_ready[mb], NBLKS);
        } else {
            spin_until(&g_uready, NUCONV);
            spin_until(&g_xready[mb], 1);
        }
    }
    __syncthreads();

    const __half* A0 = ph2 ? g_h0  : g_x0;
    const __half* B0 = ph2 ? g_w20 : g_u0;

    const uint32_t sb = smem_u32(smem);
    const int lrow = tid >> 1;
    const int lqB  = (tid & 1) * 32;
    const char* gA0 = (const char*)(A0 + (size_t)(bm + lrow) * DIM) + lqB;
    const char* gB0 = (const char*)(B0 + (size_t)(bn + lrow) * DIM) + lqB;
    const uint32_t sdst = lrow * ROWB + lqB;

    auto load_chunk = [&](int c) {
        const uint32_t st = sb + (c % NSTAGE) * STB + sdst;
        const int kb = c * BKB;
        cp16(st,            gA0 + kb); cp16(st + 16,        gA0 + kb + 16);
        cp16(st + MATB,     gB0 + kb); cp16(st + MATB + 16, gB0 + kb + 16);
        asm volatile("cp.async.commit_group;" ::: "memory");
    };

    const int lr8 = ((lane >> 3) & 1) * 8 + (lane & 7);
    const int lcb = ((lane >> 4) & 1) * 16;
    const uint32_t aRow = wm * 64 + lr8;
    const uint32_t bRow = wn * 32 + lr8;

    float acc[4][4][4];
#pragma unroll
    for (int i = 0; i < 4; i++)
#pragma unroll
        for (int j = 0; j < 4; j++)
#pragma unroll
            for (int k = 0; k < 4; k++) acc[i][j][k] = 0.0f;

    load_chunk(0);
    load_chunk(1);
    load_chunk(2);

    for (int c = 0; c < NCHUNK; c++) {
        const int rem = NCHUNK - 1 - c;
        if (rem >= 2)      asm volatile("cp.async.wait_group 2;" ::: "memory");
        else if (rem == 1) asm volatile("cp.async.wait_group 1;" ::: "memory");
        else               asm volatile("cp.async.wait_group 0;" ::: "memory");
        __syncthreads();   // chunk c visible; compute(c-1) done -> stage reusable

        if (c + 3 < NCHUNK) load_chunk(c + 3);

        const uint32_t stg = sb + (c % NSTAGE) * STB;
#pragma unroll
        for (int ks = 0; ks < 2; ks++) {
            uint32_t af[4][4], bf[2][4];
#pragma unroll
            for (int mt = 0; mt < 4; mt++)
                ldsm4(af[mt], stg + (aRow + mt * 16) * ROWB + ks * 32 + lcb);
#pragma unroll
            for (int ng = 0; ng < 2; ng++)
                ldsm4(bf[ng], stg + MATB + (bRow + ng * 16) * ROWB + ks * 32 + lcb);

#pragma unroll
            for (int mt = 0; mt < 4; mt++)
#pragma unroll
                for (int nt = 0; nt < 4; nt++) {
                    const int ng = nt >> 1, p = nt & 1;
                    mma16816(acc[mt][nt], af[mt], bf[ng][p], bf[ng][p + 2]);
                }
        }
    }

    // ---- epilogue ----
    const int r0 = bm + wm * 64 + (lane >> 2);
    const int c0 = bn + wn * 32 + (lane & 3) * 2;
    if (!ph2) {
#pragma unroll
        for (int mt = 0; mt < 4; mt++)
#pragma unroll
            for (int nt = 0; nt < 4; nt++) {
                const int col = c0 + nt * 8;
#pragma unroll
                for (int half = 0; half < 2; half++) {
                    const int row = r0 + mt * 16 + half * 8;
                    float vx = acc[mt][nt][half * 2];
                    float vy = acc[mt][nt][half * 2 + 1];
                    vx = (fabsf(vx) > 1e-3f) ? vx : 0.0f;
                    vy = (fabsf(vy) > 1e-3f) ? vy : 0.0f;
                    __half2 hv;
                    hv.x = __float2half_rn(vx);
                    hv.y = __float2half_rn(vy);
                    *(__half2*)(g_h0 + (size_t)row * DIM + col) = hv;
                }
            }
        __threadfence();
        __syncthreads();
        if (tid == 0) release_add(&g_ready[mb]);
    } else {
#pragma unroll
        for (int mt = 0; mt < 4; mt++)
#pragma unroll
            for (int nt = 0; nt < 4; nt++) {
                const int col = c0 + nt * 8;
#pragma unroll
                for (int half = 0; half < 2; half++) {
                    const int row = r0 + mt * 16 + half * 8;
                    const float2 bb = *(const float2*)&bias[col];
                    float2 v = make_float2(acc[mt][nt][half * 2] + bb.x,
                                           acc[mt][nt][half * 2 + 1] + bb.y);
                    *(float2*)(outF + (size_t)row * DIM + col) = v;
                }
            }
    }
}

// ============================================================================
// Flag reset (graph-replay safe).
// ============================================================================
__global__ void zero_flags()
{
    if (threadIdx.x < MBLKS) {
        g_ready[threadIdx.x]  = 0;
        g_xready[threadIdx.x] = 0;
    }
    if (threadIdx.x == 0) { g_p0done = 0; g_w2done = 0; g_uready = 0; }
}

// ============================================================================
// kernel_launch — inputs: x, weight, bias, U, VT; output fp32 [32768,768]
// ============================================================================
extern "C" void kernel_launch(void* const* d_in, const int* in_sizes, int n_in,
                              void* d_out, int out_size)
{
    const float* x      = (const float*)d_in[0];
    const float* weight = (const float*)d_in[1];
    const float* bias   = (const float*)d_in[2];
    const float* U      = (const float*)d_in[3];
    const float* VT     = (const float*)d_in[4];
    float* out          = (float*)d_out;

    cudaFuncSetAttribute(fused_all, cudaFuncAttributeMaxDynamicSharedMemorySize, GEMM_SMEM);

    zero_flags<<<1, 256>>>();

    // One fused kernel: converters -> phase1 -> (W2 overlapped) -> phase2,
    // acquire/release dataflow sync (all edges point to lower bids).
    fused_all<<<GRIDSZ, 256, GEMM_SMEM>>>(x, U, VT, weight, out, bias);
}

// round 14
// speedup vs baseline: 1.5705x; 1.5705x over previous
#include <cuda_runtime.h>
#include <cuda_fp16.h>
#include <stdint.h>

// ============================================================================
// SparseGradLinear fused-dataflow kernel (fp16 HMMA, fp32 accumulate):
//   convert kernels (standalone): x -> fp16, U -> fp16
//   fused grid:
//     phase1 (bids 0..1535):        h = threshold(x0 @ u0^T) -> fp16, release ready[mb]
//     W2 partials (1536..2111):     fp32 SIMT VT@weight k-split partials
//     W2 reduce  (2112..2129):      sum partials -> fp16 W2, release w2done
//     phase2 (2130..3665):          out = h @ W2^T + bias (acquire w2done, ready[mb])
// R14 = R11 + ONE change: W2 chain moved in-grid AFTER phase-1 (overlaps
// under phase-1's bulk instead of serializing in front of the kernel).
// ============================================================================

#define DIM    768
#define MROWS  32768
#define MBLKS  (MROWS / 128)    // 256
#define NBLKS  (DIM / 128)      // 6
#define NT1    (MBLKS * NBLKS)  // 1536
#define NW2P   576
#define NRED   18
#define BASEW2 NT1                  // 1536
#define BASERD (BASEW2 + NW2P)      // 2112
#define BASEP2 (BASERD + NRED)      // 2130
#define GRIDSZ (BASEP2 + NT1)       // 3666

__device__ __half    g_x0[(size_t)MROWS * DIM];
__device__ __half    g_h0[(size_t)MROWS * DIM];
__device__ __half    g_u0[DIM * DIM];
__device__ __half    g_w20[DIM * DIM];
__device__ float     g_w2part[4][DIM * DIM];
__device__ unsigned  g_ready[MBLKS];
__device__ unsigned  g_p0done;
__device__ unsigned  g_w2done;

// ---- helpers ----
__device__ __forceinline__ uint32_t smem_u32(const void* p) {
    uint32_t a;
    asm("{ .reg .u64 t; cvta.to.shared.u64 t, %1; cvt.u32.u64 %0, t; }"
        : "=r"(a) : "l"(p));
    return a;
}
__device__ __forceinline__ void cp16(uint32_t dst, const void* src) {
    asm volatile("cp.async.cg.shared.global [%0], [%1], 16;" :: "r"(dst), "l"(src));
}
__device__ __forceinline__ void ldsm4(uint32_t* r, uint32_t addr) {
    asm volatile("ldmatrix.sync.aligned.m8n8.x4.shared.b16 {%0,%1,%2,%3}, [%4];"
                 : "=r"(r[0]), "=r"(r[1]), "=r"(r[2]), "=r"(r[3]) : "r"(addr));
}
__device__ __forceinline__ void mma16816(float* d, const uint32_t* a,
                                         uint32_t b0, uint32_t b1) {
    asm volatile(
        "mma.sync.aligned.m16n8k16.row.col.f32.f16.f16.f32 "
        "{%0,%1,%2,%3}, {%4,%5,%6,%7}, {%8,%9}, {%0,%1,%2,%3};"
        : "+f"(d[0]), "+f"(d[1]), "+f"(d[2]), "+f"(d[3])
        : "r"(a[0]), "r"(a[1]), "r"(a[2]), "r"(a[3]), "r"(b0), "r"(b1));
}
__device__ __forceinline__ void spin_until(const unsigned* flag, unsigned target) {
    unsigned v;
    while (true) {
        asm volatile("ld.acquire.gpu.global.u32 %0, [%1];"
                     : "=r"(v) : "l"(flag) : "memory");
        if (v >= target) break;
        __nanosleep(200);
    }
}
__device__ __forceinline__ void release_add(unsigned* flag) {
    asm volatile("red.release.gpu.global.add.u32 [%0], 1;" :: "l"(flag) : "memory");
}

// ============================================================================
// Fused kernel — mainloop tile config
// ============================================================================
#define NCHUNK 24            // 768 / 32
#define BKB    64            // bytes of K per chunk-row (32 fp16)
#define ROWB   80            // padded row stride in bytes
#define MATB   (128 * ROWB)  // 10240 per operand tile
#define NSTAGE 4
#define STB    (2 * MATB)    // A + B per stage = 20480
#define GEMM_SMEM (NSTAGE * STB)   // 81920 -> 2 CTAs/SM

__global__ void __launch_bounds__(256, 2)
fused_all(const float* __restrict__ VT, const float* __restrict__ Wt,
          float* __restrict__ outF, const float* __restrict__ bias)
{
    extern __shared__ char smem[];
    const int bid = blockIdx.x;
    const int tid = threadIdx.x;

    // ===================== W2 partials (fp32 SIMT), mid-grid =================
    if (bid >= BASEW2 && bid < BASERD) {
        float* As = (float*)smem;                  // [16][68]
        float* Bs = (float*)(smem + 16 * 68 * 4);  // [16][64]

        const int w = bid - BASEW2;
        const int kz = w / 144;
        const int q  = w % 144;
        const int bp = (q / 12) * 64;
        const int bc = (q % 12) * 64;
        const int kbeg = kz * (DIM / 4);
        const int kend = kbeg + (DIM / 4);
        float* C = &g_w2part[kz][0];

        const int tx = tid & 15;
        const int ty = tid >> 4;

        float acc[4][4] = {};

        for (int k0 = kbeg; k0 < kend; k0 += 16) {
            {
                const int r = tid >> 2;
                const int o4 = (tid & 3) * 4;
                float4 av = *(const float4*)(VT + (size_t)(bp + r) * DIM + k0 + o4);
                As[(o4 + 0) * 68 + r] = av.x; As[(o4 + 1) * 68 + r] = av.y;
                As[(o4 + 2) * 68 + r] = av.z; As[(o4 + 3) * 68 + r] = av.w;
            }
            {
                const int o  = tid >> 4;
                const int c4 = (tid & 15) * 4;
                *(float4*)&Bs[o * 64 + c4] =
                    *(const float4*)(Wt + (size_t)(k0 + o) * DIM + bc + c4);
            }
            __syncthreads();
#pragma unroll
            for (int o = 0; o < 16; o++) {
                float a[4], b[4];
#pragma unroll
                for (int i = 0; i < 4; i++) a[i] = As[o * 68 + ty * 4 + i];
#pragma unroll
                for (int j = 0; j < 4; j++) b[j] = Bs[o * 64 + tx * 4 + j];
#pragma unroll
                for (int i = 0; i < 4; i++)
#pragma unroll
                    for (int j = 0; j < 4; j++) acc[i][j] += a[i] * b[j];
            }
            __syncthreads();
        }

#pragma unroll
        for (int i = 0; i < 4; i++)
#pragma unroll
            for (int j = 0; j < 4; j++)
                C[(size_t)(bp + ty * 4 + i) * DIM + bc + tx * 4 + j] = acc[i][j];

        __threadfence();
        __syncthreads();
        if (tid == 0) release_add(&g_p0done);
        return;
    }

    // ===================== W2 reduce -> fp16 ================================
    if (bid >= BASERD && bid < BASEP2) {
        if (tid == 0) spin_until(&g_p0done, NW2P);
        __syncthreads();

        const int r = bid - BASERD;        // 0..17
        const int n = DIM * DIM;
        const float* P = &g_w2part[0][0];
        for (int i = r * 256 + tid; i < n; i += NRED * 256) {
            float v = P[i] + P[i + n] + P[i + 2 * n] + P[i + 3 * n];
            g_w20[i] = __float2half_rn(v);
        }
        __threadfence();
        __syncthreads();
        if (tid == 0) release_add(&g_w2done);
        return;
    }

    // ===================== phases 1 & 2: main GEMMs =========================
    const bool ph2 = (bid >= BASEP2);
    const int idx = ph2 ? bid - BASEP2 : bid;
    const int mb = idx / NBLKS;
    const int nb = idx % NBLKS;
    const int bm = mb * 128;
    const int bn = nb * 128;

    const int lane = tid & 31;
    const int wid  = tid >> 5;
    const int wm   = wid >> 2;
    const int wn   = wid & 3;

    if (ph2) {
        if (tid == 0) {
            spin_until(&g_w2done, NRED);
            spin_until(&g_ready[mb], NBLKS);
        }
        __syncthreads();
    }

    const __half* A0 = ph2 ? g_h0  : g_x0;
    const __half* B0 = ph2 ? g_w20 : g_u0;

    const uint32_t sb = smem_u32(smem);
    const int lrow = tid >> 1;
    const int lqB  = (tid & 1) * 32;
    const char* gA0 = (const char*)(A0 + (size_t)(bm + lrow) * DIM) + lqB;
    const char* gB0 = (const char*)(B0 + (size_t)(bn + lrow) * DIM) + lqB;
    const uint32_t sdst = lrow * ROWB + lqB;

    auto load_chunk = [&](int c) {
        const uint32_t st = sb + (c % NSTAGE) * STB + sdst;
        const int kb = c * BKB;
        cp16(st,            gA0 + kb); cp16(st + 16,        gA0 + kb + 16);
        cp16(st + MATB,     gB0 + kb); cp16(st + MATB + 16, gB0 + kb + 16);
        asm volatile("cp.async.commit_group;" ::: "memory");
    };

    const int lr8 = ((lane >> 3) & 1) * 8 + (lane & 7);
    const int lcb = ((lane >> 4) & 1) * 16;
    const uint32_t aRow = wm * 64 + lr8;
    const uint32_t bRow = wn * 32 + lr8;

    float acc[4][4][4];
#pragma unroll
    for (int i = 0; i < 4; i++)
#pragma unroll
        for (int j = 0; j < 4; j++)
#pragma unroll
            for (int k = 0; k < 4; k++) acc[i][j][k] = 0.0f;

    load_chunk(0);
    load_chunk(1);
    load_chunk(2);

    for (int c = 0; c < NCHUNK; c++) {
        const int rem = NCHUNK - 1 - c;
        if (rem >= 2)      asm volatile("cp.async.wait_group 2;" ::: "memory");
        else if (rem == 1) asm volatile("cp.async.wait_group 1;" ::: "memory");
        else               asm volatile("cp.async.wait_group 0;" ::: "memory");
        __syncthreads();   // chunk c visible; compute(c-1) done -> stage reusable

        if (c + 3 < NCHUNK) load_chunk(c + 3);

        const uint32_t stg = sb + (c % NSTAGE) * STB;
#pragma unroll
        for (int ks = 0; ks < 2; ks++) {
            uint32_t af[4][4], bf[2][4];
#pragma unroll
            for (int mt = 0; mt < 4; mt++)
                ldsm4(af[mt], stg + (aRow + mt * 16) * ROWB + ks * 32 + lcb);
#pragma unroll
            for (int ng = 0; ng < 2; ng++)
                ldsm4(bf[ng], stg + MATB + (bRow + ng * 16) * ROWB + ks * 32 + lcb);

#pragma unroll
            for (int mt = 0; mt < 4; mt++)
#pragma unroll
                for (int nt = 0; nt < 4; nt++) {
                    const int ng = nt >> 1, p = nt & 1;
                    mma16816(acc[mt][nt], af[mt], bf[ng][p], bf[ng][p + 2]);
                }
        }
    }

    // ---- epilogue ----
    const int r0 = bm + wm * 64 + (lane >> 2);
    const int c0 = bn + wn * 32 + (lane & 3) * 2;
    if (!ph2) {
#pragma unroll
        for (int mt = 0; mt < 4; mt++)
#pragma unroll
            for (int nt = 0; nt < 4; nt++) {
                const int col = c0 + nt * 8;
#pragma unroll
                for (int half = 0; half < 2; half++) {
                    const int row = r0 + mt * 16 + half * 8;
                    float vx = acc[mt][nt][half * 2];
                    float vy = acc[mt][nt][half * 2 + 1];
                    vx = (fabsf(vx) > 1e-3f) ? vx : 0.0f;
                    vy = (fabsf(vy) > 1e-3f) ? vy : 0.0f;
                    __half2 hv;
                    hv.x = __float2half_rn(vx);
                    hv.y = __float2half_rn(vy);
                    *(__half2*)(g_h0 + (size_t)row * DIM + col) = hv;
                }
            }
        __threadfence();
        __syncthreads();
        if (tid == 0) release_add(&g_ready[mb]);
    } else {
#pragma unroll
        for (int mt = 0; mt < 4; mt++)
#pragma unroll
            for (int nt = 0; nt < 4; nt++) {
                const int col = c0 + nt * 8;
#pragma unroll
                for (int half = 0; half < 2; half++) {
                    const int row = r0 + mt * 16 + half * 8;
                    const float2 bb = *(const float2*)&bias[col];
                    float2 v = make_float2(acc[mt][nt][half * 2] + bb.x,
                                           acc[mt][nt][half * 2 + 1] + bb.y);
                    *(float2*)(outF + (size_t)row * DIM + col) = v;
                }
            }
    }
}

// ============================================================================
// Flag reset (graph-replay safe).
// ============================================================================
__global__ void zero_flags()
{
    if (threadIdx.x < MBLKS) g_ready[threadIdx.x] = 0;
    if (threadIdx.x == 0) { g_p0done = 0; g_w2done = 0; }
}

// ============================================================================
// Elementwise fp32 -> fp16 convert, float4-vectorized (standalone, as R11).
// ============================================================================
__global__ void convert_fp16(const float4* __restrict__ src,
                             __half* __restrict__ dst, int n4)
{
    int i = blockIdx.x * blockDim.x + threadIdx.x;
    if (i >= n4) return;
    float4 v = src[i];
    __half2 a, b;
    a.x = __float2half_rn(v.x); a.y = __float2half_rn(v.y);
    b.x = __float2half_rn(v.z); b.y = __float2half_rn(v.w);
    __half2* p = (__half2*)(dst + (size_t)i * 4);
    p[0] = a; p[1] = b;
}

// ============================================================================
// kernel_launch — inputs: x, weight, bias, U, VT; output fp32 [32768,768]
// ============================================================================
extern "C" void kernel_launch(void* const* d_in, const int* in_sizes, int n_in,
                              void* d_out, int out_size)
{
    const float* x      = (const float*)d_in[0];
    const float* weight = (const float*)d_in[1];
    const float* bias   = (const float*)d_in[2];
    const float* U      = (const float*)d_in[3];
    const float* VT     = (const float*)d_in[4];
    float* out          = (float*)d_out;

    __half *x0, *u0;
    cudaGetSymbolAddress((void**)&x0, g_x0);
    cudaGetSymbolAddress((void**)&u0, g_u0);

    cudaFuncSetAttribute(fused_all, cudaFuncAttributeMaxDynamicSharedMemorySize, GEMM_SMEM);

    const int M = in_sizes[0] / DIM;   // 32768

    zero_flags<<<1, 256>>>();
    {
        int n4 = M * DIM / 4;
        convert_fp16<<<(n4 + 255) / 256, 256>>>((const float4*)x, x0, n4);
    }
    {
        int n4 = DIM * DIM / 4;
        convert_fp16<<<(n4 + 255) / 256, 256>>>((const float4*)U, u0, n4);
    }

    // Fused: phase1 (leads grid) -> W2 partials+reduce (mid-grid, overlap
    // under phase1) -> phase2. All dependency edges point to lower bids.
    fused_all<<<GRIDSZ, 256, GEMM_SMEM>>>(VT, weight, out, bias);
}

// round 15
// speedup vs baseline: 1.7375x; 1.1063x over previous
#include <cuda_runtime.h>
#include <cuda_fp16.h>
#include <stdint.h>

// ============================================================================
// SparseGradLinear, fp16 HMMA pipeline (fp32 accumulate):
//   h   = threshold(fp16(x) @ fp16(U)^T)        [32768, 768]
//   out = fp16(h) @ fp16(VT @ weight)^T + bias  [32768, 768]
// R15 = R11 + persistent CTAs: 296 resident CTAs stride over the 3072-tile
// sequence (1536 phase-1, then 1536 phase-2). Consumers trail their producers
// by exactly 5.19 rounds -> near-zero spin; wave-quantization tail collapses
// to a single tile. W2 prep + converts stay as standalone kernels (R12/R14
// showed in-grid prep disrupts the producer/consumer dispatch alignment).
// ============================================================================

#define DIM    768
#define MROWS  32768
#define MBLKS  (MROWS / 128)    // 256
#define NBLKS  (DIM / 128)      // 6
#define NT1    (MBLKS * NBLKS)  // 1536
#define NTILES (2 * NT1)        // 3072
#define NPERS  296              // 2 CTAs/SM x 148 SMs

__device__ __half    g_x0[(size_t)MROWS * DIM];
__device__ __half    g_h0[(size_t)MROWS * DIM];
__device__ __half    g_u0[DIM * DIM];
__device__ __half    g_w20[DIM * DIM];
__device__ float     g_w2part[4][DIM * DIM];
__device__ unsigned  g_ready[MBLKS];

// ---- helpers ----
__device__ __forceinline__ uint32_t smem_u32(const void* p) {
    uint32_t a;
    asm("{ .reg .u64 t; cvta.to.shared.u64 t, %1; cvt.u32.u64 %0, t; }"
        : "=r"(a) : "l"(p));
    return a;
}
__device__ __forceinline__ void cp16(uint32_t dst, const void* src) {
    asm volatile("cp.async.cg.shared.global [%0], [%1], 16;" :: "r"(dst), "l"(src));
}
__device__ __forceinline__ void ldsm4(uint32_t* r, uint32_t addr) {
    asm volatile("ldmatrix.sync.aligned.m8n8.x4.shared.b16 {%0,%1,%2,%3}, [%4];"
                 : "=r"(r[0]), "=r"(r[1]), "=r"(r[2]), "=r"(r[3]) : "r"(addr));
}
__device__ __forceinline__ void mma16816(float* d, const uint32_t* a,
                                         uint32_t b0, uint32_t b1) {
    asm volatile(
        "mma.sync.aligned.m16n8k16.row.col.f32.f16.f16.f32 "
        "{%0,%1,%2,%3}, {%4,%5,%6,%7}, {%8,%9}, {%0,%1,%2,%3};"
        : "+f"(d[0]), "+f"(d[1]), "+f"(d[2]), "+f"(d[3])
        : "r"(a[0]), "r"(a[1]), "r"(a[2]), "r"(a[3]), "r"(b0), "r"(b1));
}
__device__ __forceinline__ void spin_until(const unsigned* flag, unsigned target) {
    unsigned v;
    while (true) {
        asm volatile("ld.acquire.gpu.global.u32 %0, [%1];"
                     : "=r"(v) : "l"(flag) : "memory");
        if (v >= target) break;
        __nanosleep(200);
    }
}
__device__ __forceinline__ void release_add(unsigned* flag) {
    asm volatile("red.release.gpu.global.add.u32 [%0], 1;" :: "l"(flag) : "memory");
}

// ============================================================================
// Persistent fused dual-phase tensor-core NT GEMM.
// Tile t<NT1:  h_tile = threshold(x @ U^T), fp16; release ready[mb].
// Tile t>=NT1: out_tile = h @ W2^T + bias, fp32; acquire ready[mb].
// CTA 128x128, BK=32, 256 thr, 4-stage cp.async pipeline, 80B padded rows.
// ============================================================================
#define NCHUNK 24            // 768 / 32
#define BKB    64            // bytes of K per chunk-row (32 fp16)
#define ROWB   80            // padded row stride in bytes
#define MATB   (128 * ROWB)  // 10240 per operand tile
#define NSTAGE 4
#define STB    (2 * MATB)    // A + B per stage = 20480
#define GEMM_SMEM (NSTAGE * STB)   // 81920 -> 2 CTAs/SM

__global__ void __launch_bounds__(256, 2)
fused_gemm(float* __restrict__ outF, const float* __restrict__ bias)
{
    extern __shared__ char smem[];
    const uint32_t sb = smem_u32(smem);

    const int tid  = threadIdx.x;
    const int lane = tid & 31;
    const int wid  = tid >> 5;
    const int wm   = wid >> 2;
    const int wn   = wid & 3;

    const int lr8 = ((lane >> 3) & 1) * 8 + (lane & 7);
    const int lcb = ((lane >> 4) & 1) * 16;
    const uint32_t aRow = wm * 64 + lr8;
    const uint32_t bRow = wn * 32 + lr8;

    const int lrow = tid >> 1;
    const int lqB  = (tid & 1) * 32;
    const uint32_t sdst = lrow * ROWB + lqB;

    for (int t = blockIdx.x; t < NTILES; t += NPERS) {
        const bool ph2 = (t >= NT1);
        const int idx = ph2 ? t - NT1 : t;
        const int mb = idx / NBLKS;
        const int nb = idx % NBLKS;
        const int bm = mb * 128;
        const int bn = nb * 128;

        // Phase-2: wait for the 6 producer tiles of row-block mb
        // (they sit exactly NT1 positions earlier -> ~5 rounds retired).
        if (ph2) {
            if (tid == 0) spin_until(&g_ready[mb], NBLKS);
            __syncthreads();
        }

        const __half* A0 = ph2 ? g_h0  : g_x0;
        const __half* B0 = ph2 ? g_w20 : g_u0;
        const char* gA0 = (const char*)(A0 + (size_t)(bm + lrow) * DIM) + lqB;
        const char* gB0 = (const char*)(B0 + (size_t)(bn + lrow) * DIM) + lqB;

        auto load_chunk = [&](int c) {
            const uint32_t st = sb + (c % NSTAGE) * STB + sdst;
            const int kb = c * BKB;
            cp16(st,            gA0 + kb); cp16(st + 16,        gA0 + kb + 16);
            cp16(st + MATB,     gB0 + kb); cp16(st + MATB + 16, gB0 + kb + 16);
            asm volatile("cp.async.commit_group;" ::: "memory");
        };

        float acc[4][4][4];
#pragma unroll
        for (int i = 0; i < 4; i++)
#pragma unroll
            for (int j = 0; j < 4; j++)
#pragma unroll
                for (int k = 0; k < 4; k++) acc[i][j][k] = 0.0f;

        // Prime: writes stages 0..2; previous tile's last compute used
        // stage 3 only, so no cross-tile hazard before the c=0 barrier.
        load_chunk(0);
        load_chunk(1);
        load_chunk(2);

        for (int c = 0; c < NCHUNK; c++) {
            const int rem = NCHUNK - 1 - c;
            if (rem >= 2)      asm volatile("cp.async.wait_group 2;" ::: "memory");
            else if (rem == 1) asm volatile("cp.async.wait_group 1;" ::: "memory");
            else               asm volatile("cp.async.wait_group 0;" ::: "memory");
            __syncthreads();   // chunk c visible; compute(c-1) done

            if (c + 3 < NCHUNK) load_chunk(c + 3);

            const uint32_t stg = sb + (c % NSTAGE) * STB;
#pragma unroll
            for (int ks = 0; ks < 2; ks++) {
                uint32_t af[4][4], bf[2][4];
#pragma unroll
                for (int mt = 0; mt < 4; mt++)
                    ldsm4(af[mt], stg + (aRow + mt * 16) * ROWB + ks * 32 + lcb);
#pragma unroll
                for (int ng = 0; ng < 2; ng++)
                    ldsm4(bf[ng], stg + MATB + (bRow + ng * 16) * ROWB + ks * 32 + lcb);

#pragma unroll
                for (int mt = 0; mt < 4; mt++)
#pragma unroll
                    for (int nt = 0; nt < 4; nt++) {
                        const int ng = nt >> 1, p = nt & 1;
                        mma16816(acc[mt][nt], af[mt], bf[ng][p], bf[ng][p + 2]);
                    }
            }
        }

        // ---- epilogue ----
        const int r0 = bm + wm * 64 + (lane >> 2);
        const int c0 = bn + wn * 32 + (lane & 3) * 2;
        if (!ph2) {
#pragma unroll
            for (int mt = 0; mt < 4; mt++)
#pragma unroll
                for (int nt = 0; nt < 4; nt++) {
                    const int col = c0 + nt * 8;
#pragma unroll
                    for (int half = 0; half < 2; half++) {
                        const int row = r0 + mt * 16 + half * 8;
                        float vx = acc[mt][nt][half * 2];
                        float vy = acc[mt][nt][half * 2 + 1];
                        vx = (fabsf(vx) > 1e-3f) ? vx : 0.0f;
                        vy = (fabsf(vy) > 1e-3f) ? vy : 0.0f;
                        __half2 hv;
                        hv.x = __float2half_rn(vx);
                        hv.y = __float2half_rn(vy);
                        *(__half2*)(g_h0 + (size_t)row * DIM + col) = hv;
                    }
                }
            __threadfence();
            __syncthreads();
            if (tid == 0) release_add(&g_ready[mb]);
        } else {
#pragma unroll
            for (int mt = 0; mt < 4; mt++)
#pragma unroll
                for (int nt = 0; nt < 4; nt++) {
                    const int col = c0 + nt * 8;
#pragma unroll
                    for (int half = 0; half < 2; half++) {
                        const int row = r0 + mt * 16 + half * 8;
                        const float2 bb = *(const float2*)&bias[col];
                        float2 v = make_float2(acc[mt][nt][half * 2] + bb.x,
                                               acc[mt][nt][half * 2 + 1] + bb.y);
                        *(float2*)(outF + (size_t)row * DIM + col) = v;
                    }
                }
        }
    }
}

// ============================================================================
// Flag reset (graph-replay safe).
// ============================================================================
__global__ void zero_flags()
{
    if (threadIdx.x < MBLKS) g_ready[threadIdx.x] = 0;
}

// ============================================================================
// Elementwise fp32 -> fp16 convert, float4-vectorized.
// ============================================================================
__global__ void convert_fp16(const float4* __restrict__ src,
                             __half* __restrict__ dst, int n4)
{
    int i = blockIdx.x * blockDim.x + threadIdx.x;
    if (i >= n4) return;
    float4 v = src[i];
    __half2 a, b;
    a.x = __float2half_rn(v.x); a.y = __float2half_rn(v.y);
    b.x = __float2half_rn(v.z); b.y = __float2half_rn(v.w);
    __half2* p = (__half2*)(dst + (size_t)i * 4);
    p[0] = a; p[1] = b;
}

// ============================================================================
// W2 prep, split-K: partial[z] = VT[:, zK..] @ weight[zK.., :] over K/4=192.
// Reduce sums 4 partials -> single fp16. Deterministic (no atomics).
// ============================================================================
__global__ void __launch_bounds__(256)
gemm_nn_part(const float* __restrict__ A, const float* __restrict__ B,
             float* __restrict__ Cpart, int N, int K)
{
    constexpr int BK = 16;
    __shared__ float As[BK][68];
    __shared__ float Bs[BK][64];

    const int bp = blockIdx.y * 64;
    const int bc = blockIdx.x * 64;
    const int kz = blockIdx.z;
    const int kbeg = kz * (K / 4);
    const int kend = kbeg + (K / 4);
    float* C = Cpart + (size_t)kz * N * N;

    const int t  = threadIdx.x;
    const int tx = t & 15;
    const int ty = t >> 4;

    float acc[4][4] = {};

    for (int k0 = kbeg; k0 < kend; k0 += BK) {
        {
            const int r = t >> 2;
            const int o4 = (t & 3) * 4;
            float4 av = *(const float4*)(A + (size_t)(bp + r) * K + k0 + o4);
            As[o4 + 0][r] = av.x; As[o4 + 1][r] = av.y;
            As[o4 + 2][r] = av.z; As[o4 + 3][r] = av.w;
        }
        {
            const int o  = t >> 4;
            const int c4 = (t & 15) * 4;
            *(float4*)&Bs[o][c4] = *(const float4*)(B + (size_t)(k0 + o) * N + bc + c4);
        }
        __syncthreads();
#pragma unroll
        for (int o = 0; o < BK; o++) {
            float a[4], b[4];
#pragma unroll
            for (int i = 0; i < 4; i++) a[i] = As[o][ty * 4 + i];
#pragma unroll
            for (int j = 0; j < 4; j++) b[j] = Bs[o][tx * 4 + j];
#pragma unroll
            for (int i = 0; i < 4; i++)
#pragma unroll
                for (int j = 0; j < 4; j++) acc[i][j] += a[i] * b[j];
        }
        __syncthreads();
    }

#pragma unroll
    for (int i = 0; i < 4; i++)
#pragma unroll
        for (int j = 0; j < 4; j++)
            C[(size_t)(bp + ty * 4 + i) * N + bc + tx * 4 + j] = acc[i][j];
}

__global__ void reduce_w2(const float* __restrict__ Cpart,
                          __half* __restrict__ C0, int n)
{
    int i = blockIdx.x * blockDim.x + threadIdx.x;
    if (i >= n) return;
    float v = Cpart[i] + Cpart[i + n] + Cpart[i + 2 * n] + Cpart[i + 3 * n];
    C0[i] = __float2half_rn(v);
}

// ============================================================================
// kernel_launch — inputs: x, weight, bias, U, VT; output fp32 [32768,768]
// ============================================================================
extern "C" void kernel_launch(void* const* d_in, const int* in_sizes, int n_in,
                              void* d_out, int out_size)
{
    const float* x      = (const float*)d_in[0];
    const float* weight = (const float*)d_in[1];
    const float* bias   = (const float*)d_in[2];
    const float* U      = (const float*)d_in[3];
    const float* VT     = (const float*)d_in[4];
    float* out          = (float*)d_out;

    __half *x0, *u0, *w20;
    float* w2p;
    cudaGetSymbolAddress((void**)&x0,  g_x0);
    cudaGetSymbolAddress((void**)&u0,  g_u0);
    cudaGetSymbolAddress((void**)&w20, g_w20);
    cudaGetSymbolAddress((void**)&w2p, g_w2part);

    cudaFuncSetAttribute(fused_gemm, cudaFuncAttributeMaxDynamicSharedMemorySize, GEMM_SMEM);

    const int M = in_sizes[0] / DIM;   // 32768

    zero_flags<<<1, 256>>>();
    {
        int n4 = M * DIM / 4;
        convert_fp16<<<(n4 + 255) / 256, 256>>>((const float4*)x, x0, n4);
    }
    {
        int n4 = DIM * DIM / 4;
        convert_fp16<<<(n4 + 255) / 256, 256>>>((const float4*)U, u0, n4);
    }
    gemm_nn_part<<<dim3(DIM / 64, DIM / 64, 4), 256>>>(VT, weight, w2p, DIM, DIM);
    {
        int n = DIM * DIM;
        reduce_w2<<<(n + 255) / 256, 256>>>(w2p, w20, n);
    }

    // Persistent fused GEMM1+GEMM2: 296 resident CTAs stride the 3072-tile
    // sequence; dataflow sync via per-row-block acquire/release.
    fused_gemm<<<NPERS, 256, GEMM_SMEM>>>(out, bias);
}

// round 16
// speedup vs baseline: 1.8481x; 1.0637x over previous
#include <cuda_runtime.h>
#include <cuda_fp16.h>
#include <stdint.h>

// ============================================================================
// SparseGradLinear, fp16 HMMA pipeline (fp32 accumulate):
//   h   = threshold(fp16(x) @ fp16(U)^T)        [32768, 768]
//   out = fp16(h) @ fp16(VT @ weight)^T + bias  [32768, 768]
// R16 = R11 + prep fusion: the INDEPENDENT prep jobs (x/U fp16 converts +
// W2 split-K partials) run in ONE combined kernel (no inter-CTA deps, so no
// dispatch-order hazards). reduce_w2 keeps its real dependency as a separate
// kernel. Main fused GEMM1+GEMM2 dataflow kernel is exactly R11.
// ============================================================================

#define DIM    768
#define MROWS  32768
#define MBLKS  (MROWS / 128)   // 256
#define NBLKS  (DIM / 128)     // 6
#define NT1    (MBLKS * NBLKS) // 1536

__device__ __half    g_x0[(size_t)MROWS * DIM];
__device__ __half    g_h0[(size_t)MROWS * DIM];
__device__ __half    g_u0[DIM * DIM];
__device__ __half    g_w20[DIM * DIM];
__device__ float     g_w2part[4][DIM * DIM];
__device__ unsigned  g_ready[MBLKS];

// ---- helpers ----
__device__ __forceinline__ uint32_t smem_u32(const void* p) {
    uint32_t a;
    asm("{ .reg .u64 t; cvta.to.shared.u64 t, %1; cvt.u32.u64 %0, t; }"
        : "=r"(a) : "l"(p));
    return a;
}
__device__ __forceinline__ void cp16(uint32_t dst, const void* src) {
    asm volatile("cp.async.cg.shared.global [%0], [%1], 16;" :: "r"(dst), "l"(src));
}
__device__ __forceinline__ void ldsm4(uint32_t* r, uint32_t addr) {
    asm volatile("ldmatrix.sync.aligned.m8n8.x4.shared.b16 {%0,%1,%2,%3}, [%4];"
                 : "=r"(r[0]), "=r"(r[1]), "=r"(r[2]), "=r"(r[3]) : "r"(addr));
}
__device__ __forceinline__ void mma16816(float* d, const uint32_t* a,
                                         uint32_t b0, uint32_t b1) {
    asm volatile(
        "mma.sync.aligned.m16n8k16.row.col.f32.f16.f16.f32 "
        "{%0,%1,%2,%3}, {%4,%5,%6,%7}, {%8,%9}, {%0,%1,%2,%3};"
        : "+f"(d[0]), "+f"(d[1]), "+f"(d[2]), "+f"(d[3])
        : "r"(a[0]), "r"(a[1]), "r"(a[2]), "r"(a[3]), "r"(b0), "r"(b1));
}
__device__ __forceinline__ void spin_until(const unsigned* flag, unsigned target) {
    unsigned v;
    while (true) {
        asm volatile("ld.acquire.gpu.global.u32 %0, [%1];"
                     : "=r"(v) : "l"(flag) : "memory");
        if (v >= target) break;
        __nanosleep(200);
    }
}
__device__ __forceinline__ void release_add(unsigned* flag) {
    asm volatile("red.release.gpu.global.add.u32 [%0], 1;" :: "l"(flag) : "memory");
}
__device__ __forceinline__ void cvt_store(const float4* src, __half* dst, size_t i) {
    float4 v = src[i];
    __half2 a, b;
    a.x = __float2half_rn(v.x); a.y = __float2half_rn(v.y);
    b.x = __float2half_rn(v.z); b.y = __float2half_rn(v.w);
    __half2* p = (__half2*)(dst + i * 4);
    p[0] = a; p[1] = b;
}

// ============================================================================
// prep_combo: INDEPENDENT prep jobs in one grid (no inter-CTA deps).
//   bids [0, 576):     W2 partials — partial[z] = VT[:,zK..] @ weight[zK..,:]
//   bids [576, 1600):  grid-stride fp32->fp16 converters for x then U
// ============================================================================
#define NW2P   576
#define NCVT   1024
#define PREPSZ (NW2P + NCVT)

__global__ void __launch_bounds__(256)
prep_combo(const float* __restrict__ VT, const float* __restrict__ Wt,
           const float* __restrict__ Xf, const float* __restrict__ Uf)
{
    const int bid = blockIdx.x;
    const int tid = threadIdx.x;

    if (bid < NW2P) {
        // ---- W2 partial (identical math to R11's gemm_nn_part) ----
        __shared__ float As[16][68];
        __shared__ float Bs[16][64];

        const int kz = bid / 144;
        const int q  = bid % 144;
        const int bp = (q / 12) * 64;
        const int bc = (q % 12) * 64;
        const int kbeg = kz * (DIM / 4);
        const int kend = kbeg + (DIM / 4);
        float* C = &g_w2part[kz][0];

        const int tx = tid & 15;
        const int ty = tid >> 4;

        float acc[4][4] = {};

        for (int k0 = kbeg; k0 < kend; k0 += 16) {
            {
                const int r = tid >> 2;
                const int o4 = (tid & 3) * 4;
                float4 av = *(const float4*)(VT + (size_t)(bp + r) * DIM + k0 + o4);
                As[o4 + 0][r] = av.x; As[o4 + 1][r] = av.y;
                As[o4 + 2][r] = av.z; As[o4 + 3][r] = av.w;
            }
            {
                const int o  = tid >> 4;
                const int c4 = (tid & 15) * 4;
                *(float4*)&Bs[o][c4] =
                    *(const float4*)(Wt + (size_t)(k0 + o) * DIM + bc + c4);
            }
            __syncthreads();
#pragma unroll
            for (int o = 0; o < 16; o++) {
                float a[4], b[4];
#pragma unroll
                for (int i = 0; i < 4; i++) a[i] = As[o][ty * 4 + i];
#pragma unroll
                for (int j = 0; j < 4; j++) b[j] = Bs[o][tx * 4 + j];
#pragma unroll
                for (int i = 0; i < 4; i++)
#pragma unroll
                    for (int j = 0; j < 4; j++) acc[i][j] += a[i] * b[j];
            }
            __syncthreads();
        }

#pragma unroll
        for (int i = 0; i < 4; i++)
#pragma unroll
            for (int j = 0; j < 4; j++)
                C[(size_t)(bp + ty * 4 + i) * DIM + bc + tx * 4 + j] = acc[i][j];
    } else {
        // ---- converters: grid-stride over x (then U), float4-granular ----
        const int n4x = MROWS * DIM / 4;   // 6,291,456
        const int n4u = DIM * DIM / 4;     // 147,456
        const int n4  = n4x + n4u;
        const int r = bid - NW2P;
        for (int i = r * 256 + tid; i < n4; i += NCVT * 256) {
            if (i < n4x) cvt_store((const float4*)Xf, g_x0, i);
            else         cvt_store((const float4*)Uf, g_u0, i - n4x);
        }
    }
}

// ============================================================================
// reduce_w2: sum 4 partials -> single fp16 (dependent on prep_combo).
// ============================================================================
__global__ void reduce_w2(int n)
{
    int i = blockIdx.x * blockDim.x + threadIdx.x;
    if (i >= n) return;
    const float* P = &g_w2part[0][0];
    float v = P[i] + P[i + n] + P[i + 2 * n] + P[i + 3 * n];
    g_w20[i] = __float2half_rn(v);
}

// ============================================================================
// Fused dual-phase tensor-core NT GEMM (exactly R11).
// Phase 1 (bid < NT1):  h_tile = threshold(x @ U^T), fp16; release ready[mb].
// Phase 2 (bid >= NT1): out_tile = h @ W2^T + bias, fp32; acquire ready[mb].
// CTA 128x128, BK=32, 256 thr, 4-stage cp.async pipeline, 80B padded rows.
// ============================================================================
#define NCHUNK 24            // 768 / 32
#define BKB    64            // bytes of K per chunk-row (32 fp16)
#define ROWB   80            // padded row stride in bytes
#define MATB   (128 * ROWB)  // 10240 per operand tile
#define NSTAGE 4
#define STB    (2 * MATB)    // A + B per stage = 20480
#define GEMM_SMEM (NSTAGE * STB)   // 81920 -> 2 CTAs/SM

__global__ void __launch_bounds__(256, 2)
fused_gemm(float* __restrict__ outF, const float* __restrict__ bias)
{
    extern __shared__ char smem[];
    const uint32_t sb = smem_u32(smem);

    const int bid = blockIdx.x;
    const bool ph2 = (bid >= NT1);
    const int idx = ph2 ? bid - NT1 : bid;
    const int mb = idx / NBLKS;
    const int nb = idx % NBLKS;
    const int bm = mb * 128;
    const int bn = nb * 128;

    const int tid  = threadIdx.x;
    const int lane = tid & 31;
    const int wid  = tid >> 5;
    const int wm   = wid >> 2;
    const int wn   = wid & 3;

    if (ph2) {
        if (tid == 0) spin_until(&g_ready[mb], NBLKS);
        __syncthreads();
    }

    const __half* A0 = ph2 ? g_h0  : g_x0;
    const __half* B0 = ph2 ? g_w20 : g_u0;

    const int lrow = tid >> 1;
    const int lqB  = (tid & 1) * 32;
    const char* gA0 = (const char*)(A0 + (size_t)(bm + lrow) * DIM) + lqB;
    const char* gB0 = (const char*)(B0 + (size_t)(bn + lrow) * DIM) + lqB;
    const uint32_t sdst = lrow * ROWB + lqB;

    auto load_chunk = [&](int c) {
        const uint32_t st = sb + (c % NSTAGE) * STB + sdst;
        const int kb = c * BKB;
        cp16(st,            gA0 + kb); cp16(st + 16,        gA0 + kb + 16);
        cp16(st + MATB,     gB0 + kb); cp16(st + MATB + 16, gB0 + kb + 16);
        asm volatile("cp.async.commit_group;" ::: "memory");
    };

    const int lr8 = ((lane >> 3) & 1) * 8 + (lane & 7);
    const int lcb = ((lane >> 4) & 1) * 16;
    const uint32_t aRow = wm * 64 + lr8;
    const uint32_t bRow = wn * 32 + lr8;

    float acc[4][4][4];
#pragma unroll
    for (int i = 0; i < 4; i++)
#pragma unroll
        for (int j = 0; j < 4; j++)
#pragma unroll
            for (int k = 0; k < 4; k++) acc[i][j][k] = 0.0f;

    load_chunk(0);
    load_chunk(1);
    load_chunk(2);

    for (int c = 0; c < NCHUNK; c++) {
        const int rem = NCHUNK - 1 - c;
        if (rem >= 2)      asm volatile("cp.async.wait_group 2;" ::: "memory");
        else if (rem == 1) asm volatile("cp.async.wait_group 1;" ::: "memory");
        else               asm volatile("cp.async.wait_group 0;" ::: "memory");
        __syncthreads();   // chunk c visible; compute(c-1) done -> stage reusable

        if (c + 3 < NCHUNK) load_chunk(c + 3);

        const uint32_t stg = sb + (c % NSTAGE) * STB;
#pragma unroll
        for (int ks = 0; ks < 2; ks++) {
            uint32_t af[4][4], bf[2][4];
#pragma unroll
            for (int mt = 0; mt < 4; mt++)
                ldsm4(af[mt], stg + (aRow + mt * 16) * ROWB + ks * 32 + lcb);
#pragma unroll
            for (int ng = 0; ng < 2; ng++)
                ldsm4(bf[ng], stg + MATB + (bRow + ng * 16) * ROWB + ks * 32 + lcb);

#pragma unroll
            for (int mt = 0; mt < 4; mt++)
#pragma unroll
                for (int nt = 0; nt < 4; nt++) {
                    const int ng = nt >> 1, p = nt & 1;
                    mma16816(acc[mt][nt], af[mt], bf[ng][p], bf[ng][p + 2]);
                }
        }
    }

    // ---- epilogue ----
    const int r0 = bm + wm * 64 + (lane >> 2);
    const int c0 = bn + wn * 32 + (lane & 3) * 2;
    if (!ph2) {
#pragma unroll
        for (int mt = 0; mt < 4; mt++)
#pragma unroll
            for (int nt = 0; nt < 4; nt++) {
                const int col = c0 + nt * 8;
#pragma unroll
                for (int half = 0; half < 2; half++) {
                    const int row = r0 + mt * 16 + half * 8;
                    float vx = acc[mt][nt][half * 2];
                    float vy = acc[mt][nt][half * 2 + 1];
                    vx = (fabsf(vx) > 1e-3f) ? vx : 0.0f;
                    vy = (fabsf(vy) > 1e-3f) ? vy : 0.0f;
                    __half2 hv;
                    hv.x = __float2half_rn(vx);
                    hv.y = __float2half_rn(vy);
                    *(__half2*)(g_h0 + (size_t)row * DIM + col) = hv;
                }
            }
        __threadfence();
        __syncthreads();
        if (tid == 0) release_add(&g_ready[mb]);
    } else {
#pragma unroll
        for (int mt = 0; mt < 4; mt++)
#pragma unroll
            for (int nt = 0; nt < 4; nt++) {
                const int col = c0 + nt * 8;
#pragma unroll
                for (int half = 0; half < 2; half++) {
                    const int row = r0 + mt * 16 + half * 8;
                    const float2 bb = *(const float2*)&bias[col];
                    float2 v = make_float2(acc[mt][nt][half * 2] + bb.x,
                                           acc[mt][nt][half * 2 + 1] + bb.y);
                    *(float2*)(outF + (size_t)row * DIM + col) = v;
                }
            }
    }
}

// ============================================================================
// Flag reset (graph-replay safe).
// ============================================================================
__global__ void zero_flags()
{
    if (threadIdx.x < MBLKS) g_ready[threadIdx.x] = 0;
}

// ============================================================================
// kernel_launch — inputs: x, weight, bias, U, VT; output fp32 [32768,768]
// ============================================================================
extern "C" void kernel_launch(void* const* d_in, const int* in_sizes, int n_in,
                              void* d_out, int out_size)
{
    const float* x      = (const float*)d_in[0];
    const float* weight = (const float*)d_in[1];
    const float* bias   = (const float*)d_in[2];
    const float* U      = (const float*)d_in[3];
    const float* VT     = (const float*)d_in[4];
    float* out          = (float*)d_out;

    cudaFuncSetAttribute(fused_gemm, cudaFuncAttributeMaxDynamicSharedMemorySize, GEMM_SMEM);

    zero_flags<<<1, 256>>>();

    // Independent prep (x/U converts + W2 partials) in one combined grid.
    prep_combo<<<PREPSZ, 256>>>(VT, weight, x, U);
    // Dependent: sum W2 partials -> fp16.
    reduce_w2<<<(DIM * DIM + 255) / 256, 256>>>(DIM * DIM);

    // Fused GEMM1+GEMM2 dataflow kernel (exactly R11).
    fused_gemm<<<2 * NT1, 256, GEMM_SMEM>>>(out, bias);
}

// round 17
// speedup vs baseline: 1.9458x; 1.0529x over previous
#include <cuda_runtime.h>
#include <cuda_fp16.h>
#include <stdint.h>

// ============================================================================
// SparseGradLinear, fp16 HMMA pipeline (fp32 accumulate):
//   W2  = fp16(VT) @ fp16(weight)               [768, 768]   (tensor-core!)
//   h   = threshold(fp16(x) @ fp16(U)^T)        [32768, 768]
//   out = fp16(h) @ W2^T + bias                 [32768, 768]
// R17 = R16 + W2 moved onto the tensor pipe INSIDE the fused grid:
//   36 W2 tiles (identical 128x128x768 NT shape) lead the grid; phase-2
//   acquires w2done. Deletes the fp32 W2 GEMM + reduce + 2 launch gaps.
//   prep_combo is now pure converters (x, U, VT, weight-transposed).
// ============================================================================

#define DIM    768
#define MROWS  32768
#define MBLKS  (MROWS / 128)   // 256
#define NBLKS  (DIM / 128)     // 6
#define NT1    (MBLKS * NBLKS) // 1536
#define NW2T   (NBLKS * NBLKS) // 36 W2 tiles
#define BASE1  NW2T                 // 36
#define BASE2  (BASE1 + NT1)        // 1572
#define GRIDSZ (BASE2 + NT1)        // 3108

__device__ __half    g_x0[(size_t)MROWS * DIM];
__device__ __half    g_h0[(size_t)MROWS * DIM];
__device__ __half    g_u0[DIM * DIM];
__device__ __half    g_vt[DIM * DIM];    // fp16(VT)         [p, o] o-contig
__device__ __half    g_wt[DIM * DIM];    // fp16(weight^T)   [c, o] o-contig
__device__ __half    g_w20[DIM * DIM];   // fp16 W2          [p, c] c-contig
__device__ unsigned  g_ready[MBLKS];
__device__ unsigned  g_w2done;

// ---- helpers ----
__device__ __forceinline__ uint32_t smem_u32(const void* p) {
    uint32_t a;
    asm("{ .reg .u64 t; cvta.to.shared.u64 t, %1; cvt.u32.u64 %0, t; }"
        : "=r"(a) : "l"(p));
    return a;
}
__device__ __forceinline__ void cp16(uint32_t dst, const void* src) {
    asm volatile("cp.async.cg.shared.global [%0], [%1], 16;" :: "r"(dst), "l"(src));
}
__device__ __forceinline__ void ldsm4(uint32_t* r, uint32_t addr) {
    asm volatile("ldmatrix.sync.aligned.m8n8.x4.shared.b16 {%0,%1,%2,%3}, [%4];"
                 : "=r"(r[0]), "=r"(r[1]), "=r"(r[2]), "=r"(r[3]) : "r"(addr));
}
__device__ __forceinline__ void mma16816(float* d, const uint32_t* a,
                                         uint32_t b0, uint32_t b1) {
    asm volatile(
        "mma.sync.aligned.m16n8k16.row.col.f32.f16.f16.f32 "
        "{%0,%1,%2,%3}, {%4,%5,%6,%7}, {%8,%9}, {%0,%1,%2,%3};"
        : "+f"(d[0]), "+f"(d[1]), "+f"(d[2]), "+f"(d[3])
        : "r"(a[0]), "r"(a[1]), "r"(a[2]), "r"(a[3]), "r"(b0), "r"(b1));
}
__device__ __forceinline__ void spin_until(const unsigned* flag, unsigned target) {
    unsigned v;
    while (true) {
        asm volatile("ld.acquire.gpu.global.u32 %0, [%1];"
                     : "=r"(v) : "l"(flag) : "memory");
        if (v >= target) break;
        __nanosleep(200);
    }
}
__device__ __forceinline__ void release_add(unsigned* flag) {
    asm volatile("red.release.gpu.global.add.u32 [%0], 1;" :: "l"(flag) : "memory");
}
__device__ __forceinline__ void cvt_store(const float4* src, __half* dst, size_t i) {
    float4 v = src[i];
    __half2 a, b;
    a.x = __float2half_rn(v.x); a.y = __float2half_rn(v.y);
    b.x = __float2half_rn(v.z); b.y = __float2half_rn(v.w);
    __half2* p = (__half2*)(dst + i * 4);
    p[0] = a; p[1] = b;
}

// ============================================================================
// prep_combo: pure converters, all independent.
//   bids [0, NTRP):       weight transpose+convert via 64x65 smem tiles
//   bids [NTRP, PREPSZ):  grid-stride fp32->fp16 convert of x, U, VT
// ============================================================================
#define NTRP   144             // 12x12 transpose tiles of 64x64
#define NCVT   1024
#define PREPSZ (NTRP + NCVT)

__global__ void __launch_bounds__(256)
prep_combo(const float* __restrict__ Xf, const float* __restrict__ Uf,
           const float* __restrict__ VTf, const float* __restrict__ Wf)
{
    const int bid = blockIdx.x;
    const int tid = threadIdx.x;

    if (bid < NTRP) {
        // ---- weight[o,c] -> g_wt[c,o] (fp16), 64x64 tile via smem ----
        __shared__ float s[64][65];
        const int ob0 = (bid / 12) * 64;
        const int cb0 = (bid % 12) * 64;
        for (int idx = tid; idx < 64 * 64; idx += 256) {
            const int r = idx >> 6, c = idx & 63;
            s[r][c] = Wf[(size_t)(ob0 + r) * DIM + cb0 + c];   // coalesced read
        }
        __syncthreads();
        for (int idx = tid; idx < 64 * 64; idx += 256) {
            const int r2 = idx >> 6, c2 = idx & 63;
            // s[c2][r2]: stride-65 across lanes -> conflict-free (65 odd)
            g_wt[(size_t)(cb0 + r2) * DIM + ob0 + c2] = __float2half_rn(s[c2][r2]);
        }
    } else {
        // ---- x, U, VT converts, float4-granular grid-stride ----
        const int n4x = MROWS * DIM / 4;   // 6,291,456
        const int n4m = DIM * DIM / 4;     // 147,456 (U and VT each)
        const int n4  = n4x + 2 * n4m;
        const int r = bid - NTRP;
        for (int i = r * 256 + tid; i < n4; i += NCVT * 256) {
            if (i < n4x)            cvt_store((const float4*)Xf,  g_x0, i);
            else if (i < n4x + n4m) cvt_store((const float4*)Uf,  g_u0, i - n4x);
            else                    cvt_store((const float4*)VTf, g_vt, i - n4x - n4m);
        }
    }
}

// ============================================================================
// Fused triple-phase tensor-core NT GEMM. All tiles are 128x128x768 NT.
//   W2 tiles (bid < 36):      W2 = VT @ wt^T, fp16 out; release w2done.
//   Phase 1 (36..1571):       h = threshold(x @ U^T), fp16; release ready[mb].
//   Phase 2 (1572..3107):     out = h @ W2^T + bias, fp32; acquire both.
// CTA 128x128, BK=32, 256 thr, 4-stage cp.async pipeline, 80B padded rows.
// ============================================================================
#define NCHUNK 24            // 768 / 32
#define BKB    64            // bytes of K per chunk-row (32 fp16)
#define ROWB   80            // padded row stride in bytes
#define MATB   (128 * ROWB)  // 10240 per operand tile
#define NSTAGE 4
#define STB    (2 * MATB)    // A + B per stage = 20480
#define GEMM_SMEM (NSTAGE * STB)   // 81920 -> 2 CTAs/SM

__global__ void __launch_bounds__(256, 2)
fused_gemm(float* __restrict__ outF, const float* __restrict__ bias)
{
    extern __shared__ char smem[];
    const uint32_t sb = smem_u32(smem);

    const int bid = blockIdx.x;
    const int tid  = threadIdx.x;
    const int lane = tid & 31;
    const int wid  = tid >> 5;
    const int wm   = wid >> 2;
    const int wn   = wid & 3;

    // mode: 0 = W2 tile, 1 = phase-1, 2 = phase-2
    int mode, mb, nb;
    if (bid < BASE1)      { mode = 0; mb = bid / NBLKS;            nb = bid % NBLKS; }
    else if (bid < BASE2) { mode = 1; mb = (bid - BASE1) / NBLKS;  nb = (bid - BASE1) % NBLKS; }
    else                  { mode = 2; mb = (bid - BASE2) / NBLKS;  nb = (bid - BASE2) % NBLKS; }
    const int bm = mb * 128;
    const int bn = nb * 128;

    if (mode == 2) {
        if (tid == 0) {
            spin_until(&g_w2done, NW2T);
            spin_until(&g_ready[mb], NBLKS);
        }
        __syncthreads();
    }

    const __half* A0 = (mode == 0) ? g_vt : (mode == 1) ? g_x0 : g_h0;
    const __half* B0 = (mode == 0) ? g_wt : (mode == 1) ? g_u0 : g_w20;

    const int lrow = tid >> 1;
    const int lqB  = (tid & 1) * 32;
    const char* gA0 = (const char*)(A0 + (size_t)(bm + lrow) * DIM) + lqB;
    const char* gB0 = (const char*)(B0 + (size_t)(bn + lrow) * DIM) + lqB;
    const uint32_t sdst = lrow * ROWB + lqB;

    auto load_chunk = [&](int c) {
        const uint32_t st = sb + (c % NSTAGE) * STB + sdst;
        const int kb = c * BKB;
        cp16(st,            gA0 + kb); cp16(st + 16,        gA0 + kb + 16);
        cp16(st + MATB,     gB0 + kb); cp16(st + MATB + 16, gB0 + kb + 16);
        asm volatile("cp.async.commit_group;" ::: "memory");
    };

    const int lr8 = ((lane >> 3) & 1) * 8 + (lane & 7);
    const int lcb = ((lane >> 4) & 1) * 16;
    const uint32_t aRow = wm * 64 + lr8;
    const uint32_t bRow = wn * 32 + lr8;

    float acc[4][4][4];
#pragma unroll
    for (int i = 0; i < 4; i++)
#pragma unroll
        for (int j = 0; j < 4; j++)
#pragma unroll
            for (int k = 0; k < 4; k++) acc[i][j][k] = 0.0f;

    load_chunk(0);
    load_chunk(1);
    load_chunk(2);

    for (int c = 0; c < NCHUNK; c++) {
        const int rem = NCHUNK - 1 - c;
        if (rem >= 2)      asm volatile("cp.async.wait_group 2;" ::: "memory");
        else if (rem == 1) asm volatile("cp.async.wait_group 1;" ::: "memory");
        else               asm volatile("cp.async.wait_group 0;" ::: "memory");
        __syncthreads();   // chunk c visible; compute(c-1) done -> stage reusable

        if (c + 3 < NCHUNK) load_chunk(c + 3);

        const uint32_t stg = sb + (c % NSTAGE) * STB;
#pragma unroll
        for (int ks = 0; ks < 2; ks++) {
            uint32_t af[4][4], bf[2][4];
#pragma unroll
            for (int mt = 0; mt < 4; mt++)
                ldsm4(af[mt], stg + (aRow + mt * 16) * ROWB + ks * 32 + lcb);
#pragma unroll
            for (int ng = 0; ng < 2; ng++)
                ldsm4(bf[ng], stg + MATB + (bRow + ng * 16) * ROWB + ks * 32 + lcb);

#pragma unroll
            for (int mt = 0; mt < 4; mt++)
#pragma unroll
                for (int nt = 0; nt < 4; nt++) {
                    const int ng = nt >> 1, p = nt & 1;
                    mma16816(acc[mt][nt], af[mt], bf[ng][p], bf[ng][p + 2]);
                }
        }
    }

    // ---- epilogue ----
    const int r0 = bm + wm * 64 + (lane >> 2);
    const int c0 = bn + wn * 32 + (lane & 3) * 2;
    if (mode == 0) {
        // W2 tile: fp16 store, release w2done
#pragma unroll
        for (int mt = 0; mt < 4; mt++)
#pragma unroll
            for (int nt = 0; nt < 4; nt++) {
                const int col = c0 + nt * 8;
#pragma unroll
                for (int half = 0; half < 2; half++) {
                    const int row = r0 + mt * 16 + half * 8;
                    __half2 hv;
                    hv.x = __float2half_rn(acc[mt][nt][half * 2]);
                    hv.y = __float2half_rn(acc[mt][nt][half * 2 + 1]);
                    *(__half2*)(g_w20 + (size_t)row * DIM + col) = hv;
                }
            }
        __threadfence();
        __syncthreads();
        if (tid == 0) release_add(&g_w2done);
    } else if (mode == 1) {
#pragma unroll
        for (int mt = 0; mt < 4; mt++)
#pragma unroll
            for (int nt = 0; nt < 4; nt++) {
                const int col = c0 + nt * 8;
#pragma unroll
                for (int half = 0; half < 2; half++) {
                    const int row = r0 + mt * 16 + half * 8;
                    float vx = acc[mt][nt][half * 2];
                    float vy = acc[mt][nt][half * 2 + 1];
                    vx = (fabsf(vx) > 1e-3f) ? vx : 0.0f;
                    vy = (fabsf(vy) > 1e-3f) ? vy : 0.0f;
                    __half2 hv;
                    hv.x = __float2half_rn(vx);
                    hv.y = __float2half_rn(vy);
                    *(__half2*)(g_h0 + (size_t)row * DIM + col) = hv;
                }
            }
        __threadfence();
        __syncthreads();
        if (tid == 0) release_add(&g_ready[mb]);
    } else {
#pragma unroll
        for (int mt = 0; mt < 4; mt++)
#pragma unroll
            for (int nt = 0; nt < 4; nt++) {
                const int col = c0 + nt * 8;
#pragma unroll
                for (int half = 0; half < 2; half++) {
                    const int row = r0 + mt * 16 + half * 8;
                    const float2 bb = *(const float2*)&bias[col];
                    float2 v = make_float2(acc[mt][nt][half * 2] + bb.x,
                                           acc[mt][nt][half * 2 + 1] + bb.y);
                    *(float2*)(outF + (size_t)row * DIM + col) = v;
                }
            }
    }
}

// ============================================================================
// Flag reset (graph-replay safe).
// ============================================================================
__global__ void zero_flags()
{
    if (threadIdx.x < MBLKS) g_ready[threadIdx.x] = 0;
    if (threadIdx.x == 0) g_w2done = 0;
}

// ============================================================================
// kernel_launch — inputs: x, weight, bias, U, VT; output fp32 [32768,768]
// ============================================================================
extern "C" void kernel_launch(void* const* d_in, const int* in_sizes, int n_in,
                              void* d_out, int out_size)
{
    const float* x      = (const float*)d_in[0];
    const float* weight = (const float*)d_in[1];
    const float* bias   = (const float*)d_in[2];
    const float* U      = (const float*)d_in[3];
    const float* VT     = (const float*)d_in[4];
    float* out          = (float*)d_out;

    cudaFuncSetAttribute(fused_gemm, cudaFuncAttributeMaxDynamicSharedMemorySize, GEMM_SMEM);

    zero_flags<<<1, 256>>>();

    // Pure converters (x, U, VT, weight-transpose) — all independent.
    prep_combo<<<PREPSZ, 256>>>(x, U, VT, weight);

    // Fused W2 + GEMM1 + GEMM2 dataflow kernel.
    fused_gemm<<<GRIDSZ, 256, GEMM_SMEM>>>(out, bias);
}